// round 1
// baseline (speedup 1.0000x reference)
#include <cuda_runtime.h>

#define N_ROWS 256
#define D_COLS 8192
#define LAMBDA 0.005f
#define SPLITS 16
#define KCHUNK (D_COLS / SPLITS)   // 512
#define NPAIRS 10                  // upper-triangular 64x64 tile pairs of a 256x256 matrix

// ---- scratch (static __device__ allocations are allowed) ----
__device__ float g_mu[2][D_COLS];
__device__ float g_inv[2][D_COLS];
__device__ float g_diag[32];                    // per-block partials of diagonal term
__device__ float g_GP[2][SPLITS][256 * 256];    // Gram K-split partials (upper tiles only)
__device__ float g_red[2 * NPAIRS * SPLITS];    // oversized; only [0,160) used
__device__ const int PTI[NPAIRS] = {0, 0, 0, 0, 1, 1, 1, 2, 2, 3};
__device__ const int PTJ[NPAIRS] = {0, 1, 2, 3, 1, 2, 3, 2, 3, 3};

// ---------------------------------------------------------------------------
// Kernel A: per-column stats (mean, unbiased inv-std) + diagonal loss term.
// 32 blocks x 256 threads; thread <-> column, fully coalesced.
// ---------------------------------------------------------------------------
__global__ void stats_kernel(const float* __restrict__ za, const float* __restrict__ zb) {
    const int col = blockIdx.x * 256 + threadIdx.x;
    float sa = 0.f, sb = 0.f, saa = 0.f, sbb = 0.f, sab = 0.f;
#pragma unroll 8
    for (int n = 0; n < N_ROWS; ++n) {
        float a = za[n * D_COLS + col];
        float b = zb[n * D_COLS + col];
        sa += a; sb += b;
        saa += a * a; sbb += b * b; sab += a * b;
    }
    const float mua = sa * (1.f / 256.f);
    const float mub = sb * (1.f / 256.f);
    const float vara = (saa - sa * mua) * (1.f / 255.f);
    const float varb = (sbb - sb * mub) * (1.f / 255.f);
    const float ia = rsqrtf(vara);
    const float ib = rsqrtf(varb);
    g_mu[0][col] = mua; g_inv[0][col] = ia;
    g_mu[1][col] = mub; g_inv[1][col] = ib;

    // c_dd = (1/N) * sum_n ((a-mua)/sa_) * ((b-mub)/sb_) = (sab - N*mua*mub)*ia*ib/N
    const float c = (sab - 256.f * mua * mub) * ia * ib * (1.f / 256.f);
    float term = (c - 1.f) * (c - 1.f) - LAMBDA * c * c;

    __shared__ float sm[256];
    sm[threadIdx.x] = term;
    __syncthreads();
#pragma unroll
    for (int off = 128; off > 0; off >>= 1) {
        if (threadIdx.x < off) sm[threadIdx.x] += sm[threadIdx.x + off];
        __syncthreads();
    }
    if (threadIdx.x == 0) g_diag[blockIdx.x] = sm[0];
}

// ---------------------------------------------------------------------------
// Kernel B: Gram partials. G = Znorm * Znorm^T (256x256), K = 8192 split 16x.
// Grid: 2 arrays * 10 upper tile pairs * 16 K-splits = 320 blocks, 256 thr.
// 64x64 tile per block, 4x4 microtile per thread, normalize-on-the-fly.
// Row assignment stride-16 => conflict-free float4 LDS (row stride 36 floats
// = 9 quad-banks, odd, so 8-thread phases cycle through all bank quads).
// ---------------------------------------------------------------------------
__global__ void gram_kernel(const float* __restrict__ za, const float* __restrict__ zb) {
    const int b = blockIdx.x;
    const int sel = b / (NPAIRS * SPLITS);
    const int rem = b % (NPAIRS * SPLITS);
    const int pair = rem / SPLITS;
    const int s = rem % SPLITS;
    const int ti = PTI[pair], tj = PTJ[pair];

    const float* __restrict__ Z = sel ? zb : za;
    const float* __restrict__ mu = g_mu[sel];
    const float* __restrict__ iv = g_inv[sel];
    float* __restrict__ out = g_GP[sel][s];

    __shared__ __align__(16) float As[64][36];
    __shared__ __align__(16) float Bs[64][36];

    const int tid = threadIdx.x;
    const int tx = tid & 15;
    const int ty = tid >> 4;

    float acc[4][4] = {};

    const int k0 = s * KCHUNK;
    for (int kk = 0; kk < KCHUNK; kk += 32) {
#pragma unroll
        for (int l = 0; l < 8; ++l) {
            const int idx = l * 256 + tid;
            const int r = idx >> 5;
            const int k = idx & 31;
            const int kg = k0 + kk + k;
            const float m = mu[kg];
            const float w = iv[kg];
            As[r][k] = (Z[(ti * 64 + r) * D_COLS + kg] - m) * w;
            Bs[r][k] = (Z[(tj * 64 + r) * D_COLS + kg] - m) * w;
        }
        __syncthreads();
#pragma unroll
        for (int k = 0; k < 32; k += 4) {
            float4 av[4], bv[4];
#pragma unroll
            for (int i = 0; i < 4; ++i) av[i] = *(const float4*)&As[ty + i * 16][k];
#pragma unroll
            for (int j = 0; j < 4; ++j) bv[j] = *(const float4*)&Bs[tx + j * 16][k];
#pragma unroll
            for (int i = 0; i < 4; ++i)
#pragma unroll
                for (int j = 0; j < 4; ++j) {
                    acc[i][j] += av[i].x * bv[j].x;
                    acc[i][j] += av[i].y * bv[j].y;
                    acc[i][j] += av[i].z * bv[j].z;
                    acc[i][j] += av[i].w * bv[j].w;
                }
        }
        __syncthreads();
    }

#pragma unroll
    for (int i = 0; i < 4; ++i)
#pragma unroll
        for (int j = 0; j < 4; ++j) {
            const int gi = ti * 64 + ty + i * 16;
            const int gj = tj * 64 + tx + j * 16;
            out[gi * 256 + gj] = acc[i][j];
        }
}

// ---------------------------------------------------------------------------
// Kernel C: reduce  sum_{upper tiles} w * Ga[i][j] * Gb[i][j]  (w=2 off-diag
// tiles, 1 diag tiles; both Grams symmetric so this equals the full sum).
// 160 blocks x 256 threads; one element per thread, 16+16 split partials.
// ---------------------------------------------------------------------------
__global__ void cross_kernel() {
    const int b = blockIdx.x;          // 0..159
    const int pair = b >> 4;
    const int sub = b & 15;
    const int ti = PTI[pair], tj = PTJ[pair];
    const int e = sub * 256 + threadIdx.x;   // 0..4095 within 64x64 tile
    const int li = e >> 6, lj = e & 63;
    const int idx = (ti * 64 + li) * 256 + (tj * 64 + lj);

    float ga = 0.f, gb = 0.f;
#pragma unroll
    for (int s2 = 0; s2 < SPLITS; ++s2) {
        ga += g_GP[0][s2][idx];
        gb += g_GP[1][s2][idx];
    }
    const float w = (ti == tj) ? 1.f : 2.f;
    float v = w * ga * gb;

    __shared__ float sm[256];
    sm[threadIdx.x] = v;
    __syncthreads();
#pragma unroll
    for (int off = 128; off > 0; off >>= 1) {
        if (threadIdx.x < off) sm[threadIdx.x] += sm[threadIdx.x + off];
        __syncthreads();
    }
    if (threadIdx.x == 0) g_red[b] = sm[0];
}

// ---------------------------------------------------------------------------
// Kernel D: final combine. loss = (lambda/N^2)*trace_part + diag_part
// ---------------------------------------------------------------------------
__global__ void final_kernel(float* __restrict__ out) {
    const int t = threadIdx.x;
    float v = 0.f;
    if (t < 160) v += g_red[t] * (LAMBDA / (256.f * 256.f));
    if (t < 32) v += g_diag[t];

    __shared__ float sm[256];
    sm[t] = v;
    __syncthreads();
#pragma unroll
    for (int off = 128; off > 0; off >>= 1) {
        if (t < off) sm[t] += sm[t + off];
        __syncthreads();
    }
    if (t == 0) out[0] = sm[0];
}

// ---------------------------------------------------------------------------
extern "C" void kernel_launch(void* const* d_in, const int* in_sizes, int n_in,
                              void* d_out, int out_size) {
    const float* za = (const float*)d_in[0];
    const float* zb = (const float*)d_in[1];
    float* out = (float*)d_out;

    stats_kernel<<<D_COLS / 256, 256>>>(za, zb);
    gram_kernel<<<2 * NPAIRS * SPLITS, 256>>>(za, zb);
    cross_kernel<<<NPAIRS * SPLITS, 256>>>();
    final_kernel<<<1, 256>>>(out);
}

// round 2
// speedup vs baseline: 2.0879x; 2.0879x over previous
#include <cuda_runtime.h>
#include <cuda_bf16.h>

#define N_ROWS 256
#define D_COLS 8192
#define LAMBDA 0.005f
#define SPLITS 24
#define NTILES 3            // symmetric 128x128 tile pairs: (0,0),(0,1),(1,1)
#define TILE_ELEMS 16384    // 128*128
#define LDB 40              // smem row stride in bf16 (80B = 20 banks -> conflict-free ldmatrix)

// ---- scratch ----
__device__ __align__(16) float g_mu[2][D_COLS];
__device__ __align__(16) float g_inv[2][D_COLS];
__device__ float g_diag[64];
__device__ __align__(16) float g_GP[2][SPLITS][NTILES * TILE_ELEMS];  // 9.4 MB partials
__device__ float g_red[48];

// ---------------------------------------------------------------------------
// Kernel A: per-column stats + exact diagonal loss term (fp32, one pass).
// 64 blocks x 128 threads, thread <-> column, coalesced.
// ---------------------------------------------------------------------------
__global__ void stats_kernel(const float* __restrict__ za, const float* __restrict__ zb) {
    const int col = blockIdx.x * 128 + threadIdx.x;
    float sa = 0.f, sb = 0.f, saa = 0.f, sbb = 0.f, sab = 0.f;
#pragma unroll 8
    for (int n = 0; n < N_ROWS; ++n) {
        float a = za[n * D_COLS + col];
        float b = zb[n * D_COLS + col];
        sa += a; sb += b;
        saa += a * a; sbb += b * b; sab += a * b;
    }
    const float mua = sa * (1.f / 256.f);
    const float mub = sb * (1.f / 256.f);
    const float ia = rsqrtf((saa - sa * mua) * (1.f / 255.f));
    const float ib = rsqrtf((sbb - sb * mub) * (1.f / 255.f));
    g_mu[0][col] = mua; g_inv[0][col] = ia;
    g_mu[1][col] = mub; g_inv[1][col] = ib;

    const float c = (sab - 256.f * mua * mub) * ia * ib * (1.f / 256.f);
    float term = (c - 1.f) * (c - 1.f) - LAMBDA * c * c;

    __shared__ float sm[128];
    sm[threadIdx.x] = term;
    __syncthreads();
#pragma unroll
    for (int off = 64; off > 0; off >>= 1) {
        if (threadIdx.x < off) sm[threadIdx.x] += sm[threadIdx.x + off];
        __syncthreads();
    }
    if (threadIdx.x == 0) g_diag[blockIdx.x] = sm[0];
}

// ---------------------------------------------------------------------------
// Tensor-core Gram kernel: G = Znorm * Znorm^T (256x256), bf16 in / fp32 acc.
// Grid: 2 matrices x 3 tile pairs x 24 K-splits = 144 blocks (1 wave / 148 SM)
// Block: 256 thr (8 warps), tile 128x128, warp tile 32x64, BK=32.
// K split: 256 k-iters of 32 -> splits 0..15 get 11 iters, 16..23 get 10.
// ---------------------------------------------------------------------------
__device__ __forceinline__ void mma_bf16(float* c, const unsigned* a, unsigned b0, unsigned b1) {
    asm volatile(
        "mma.sync.aligned.m16n8k16.row.col.f32.bf16.bf16.f32 "
        "{%0,%1,%2,%3}, {%4,%5,%6,%7}, {%8,%9}, {%0,%1,%2,%3};\n"
        : "+f"(c[0]), "+f"(c[1]), "+f"(c[2]), "+f"(c[3])
        : "r"(a[0]), "r"(a[1]), "r"(a[2]), "r"(a[3]), "r"(b0), "r"(b1));
}
__device__ __forceinline__ void ldm4(unsigned* r, unsigned addr) {
    asm volatile("ldmatrix.sync.aligned.m8n8.x4.shared.b16 {%0,%1,%2,%3}, [%4];\n"
        : "=r"(r[0]), "=r"(r[1]), "=r"(r[2]), "=r"(r[3]) : "r"(addr));
}

__global__ __launch_bounds__(256, 1)
void gram_kernel(const float* __restrict__ za, const float* __restrict__ zb) {
    __shared__ __align__(16) __nv_bfloat16 sA[128 * LDB];
    __shared__ __align__(16) __nv_bfloat16 sB[128 * LDB];

    const int b = blockIdx.x;
    const int sel = b / (NTILES * SPLITS);
    const int rem = b % (NTILES * SPLITS);
    const int pair = rem / SPLITS;
    const int s = rem % SPLITS;

    const float* __restrict__ Z = sel ? zb : za;
    const float* __restrict__ mu = g_mu[sel];
    const float* __restrict__ iv = g_inv[sel];

    const int m0 = (pair == 2) ? 128 : 0;
    const int n0 = (pair == 0) ? 0 : 128;

    const int ks = (s < 16) ? s * 11 : 176 + (s - 16) * 10;
    const int kn = (s < 16) ? 11 : 10;

    const int tid = threadIdx.x;
    const int warp = tid >> 5;
    const int lane = tid & 31;
    const int wm = warp & 3;   // m strip of 32
    const int wn = warp >> 2;  // n strip of 64

    float acc[2][8][4];
#pragma unroll
    for (int i = 0; i < 2; ++i)
#pragma unroll
        for (int j = 0; j < 8; ++j)
#pragma unroll
            for (int k = 0; k < 4; ++k) acc[i][j][k] = 0.f;

    // ldmatrix per-lane address offsets
    const unsigned aBase = (unsigned)__cvta_generic_to_shared(sA);
    const unsigned bBase = (unsigned)__cvta_generic_to_shared(sB);
    const int laR = (lane & 7) + (lane & 8);         // A: rows 0-7/8-15, +8 for lanes 8-15,24-31
    const int laC = (lane >> 1) & 8;                 // A: col +8 for lanes >= 16
    const int lbR = (lane & 7) + ((lane >> 1) & 8);  // B: rows +8 for lanes >= 16
    const int lbC = (lane & 8);                      // B: col +8 for lanes 8-15,24-31
    const unsigned aAddr = aBase + (unsigned)(((wm * 32 + laR) * LDB + laC) * 2);
    const unsigned bAddr = bBase + (unsigned)(((wn * 64 + lbR) * LDB + lbC) * 2);

    const float* __restrict__ Zm = Z + m0 * D_COLS;
    const float* __restrict__ Zn = Z + n0 * D_COLS;

    for (int it = 0; it < kn; ++it) {
        const int k0 = (ks + it) * 32;

        // Stage: load 128x32 fp32 per side, normalize, convert bf16, store.
#pragma unroll
        for (int l = 0; l < 4; ++l) {
            const int f = l * 256 + tid;    // 0..1023 float4 slots
            const int row = f >> 3;
            const int c4 = f & 7;
            const int kg = k0 + c4 * 4;
            const float4 mm = *(const float4*)&mu[kg];
            const float4 ww = *(const float4*)&iv[kg];

            float4 va = *(const float4*)&Zm[row * D_COLS + kg];
            union { __nv_bfloat162 h2[2]; uint2 u; } pa;
            pa.h2[0] = __floats2bfloat162_rn((va.x - mm.x) * ww.x, (va.y - mm.y) * ww.y);
            pa.h2[1] = __floats2bfloat162_rn((va.z - mm.z) * ww.z, (va.w - mm.w) * ww.w);
            *(uint2*)&sA[row * LDB + c4 * 4] = pa.u;

            float4 vb = *(const float4*)&Zn[row * D_COLS + kg];
            union { __nv_bfloat162 h2[2]; uint2 u; } pb;
            pb.h2[0] = __floats2bfloat162_rn((vb.x - mm.x) * ww.x, (vb.y - mm.y) * ww.y);
            pb.h2[1] = __floats2bfloat162_rn((vb.z - mm.z) * ww.z, (vb.w - mm.w) * ww.w);
            *(uint2*)&sB[row * LDB + c4 * 4] = pb.u;
        }
        __syncthreads();

        // Compute: 2 k-frags of 16; per warp 2 m-frags x 8 n-frags
#pragma unroll
        for (int kf = 0; kf < 2; ++kf) {
            unsigned A0[4], A1[4];
            ldm4(A0, aAddr + (unsigned)((kf * 16) * 2));
            ldm4(A1, aAddr + (unsigned)((16 * LDB + kf * 16) * 2));
#pragma unroll
            for (int fp = 0; fp < 4; ++fp) {
                unsigned B[4];
                ldm4(B, bAddr + (unsigned)((fp * 16 * LDB + kf * 16) * 2));
                mma_bf16(acc[0][2 * fp],     A0, B[0], B[1]);
                mma_bf16(acc[0][2 * fp + 1], A0, B[2], B[3]);
                mma_bf16(acc[1][2 * fp],     A1, B[0], B[1]);
                mma_bf16(acc[1][2 * fp + 1], A1, B[2], B[3]);
            }
        }
        __syncthreads();
    }

    // Write 128x128 partial tile
    float* __restrict__ outp = &g_GP[sel][s][pair * TILE_ELEMS];
#pragma unroll
    for (int fm = 0; fm < 2; ++fm)
#pragma unroll
        for (int fn = 0; fn < 8; ++fn) {
            const int i = wm * 32 + fm * 16 + (lane >> 2);
            const int j = wn * 64 + fn * 8 + (lane & 3) * 2;
            float2 lo = {acc[fm][fn][0], acc[fm][fn][1]};
            float2 hi = {acc[fm][fn][2], acc[fm][fn][3]};
            *(float2*)&outp[i * 128 + j] = lo;
            *(float2*)&outp[(i + 8) * 128 + j] = hi;
        }
}

// ---------------------------------------------------------------------------
// Kernel C: sum splits, then sum w * Ga .* Gb over the 3 stored tiles
// (w=2 for the off-diagonal tile pair; G symmetric). 48 blocks x 256 thr,
// one float4 of elements per thread.
// ---------------------------------------------------------------------------
__global__ void cross_kernel() {
    const int t = blockIdx.x * 256 + threadIdx.x;  // 0..12287 float4 tasks
    const int pair = t >> 12;                      // 4096 float4 per tile
    const float w = (pair == 1) ? 2.f : 1.f;

    float4 ga = {0.f, 0.f, 0.f, 0.f}, gb = {0.f, 0.f, 0.f, 0.f};
#pragma unroll
    for (int s = 0; s < SPLITS; ++s) {
        const float4 a = *(const float4*)&g_GP[0][s][t * 4];
        const float4 bb = *(const float4*)&g_GP[1][s][t * 4];
        ga.x += a.x; ga.y += a.y; ga.z += a.z; ga.w += a.w;
        gb.x += bb.x; gb.y += bb.y; gb.z += bb.z; gb.w += bb.w;
    }
    float v = w * (ga.x * gb.x + ga.y * gb.y + ga.z * gb.z + ga.w * gb.w);

    __shared__ float sm[256];
    sm[threadIdx.x] = v;
    __syncthreads();
#pragma unroll
    for (int off = 128; off > 0; off >>= 1) {
        if (threadIdx.x < off) sm[threadIdx.x] += sm[threadIdx.x + off];
        __syncthreads();
    }
    if (threadIdx.x == 0) g_red[blockIdx.x] = sm[0];
}

// ---------------------------------------------------------------------------
// Kernel D: final combine. loss = (lambda/N^2) * cross + diag
// ---------------------------------------------------------------------------
__global__ void final_kernel(float* __restrict__ out) {
    const int t = threadIdx.x;
    float v = 0.f;
    if (t < 48) v = g_red[t] * (LAMBDA / (256.f * 256.f));
    if (t < 64) v += g_diag[t];

    __shared__ float sm[128];
    sm[t] = v;
    __syncthreads();
#pragma unroll
    for (int off = 64; off > 0; off >>= 1) {
        if (t < off) sm[t] += sm[t + off];
        __syncthreads();
    }
    if (t == 0) out[0] = sm[0];
}

// ---------------------------------------------------------------------------
extern "C" void kernel_launch(void* const* d_in, const int* in_sizes, int n_in,
                              void* d_out, int out_size) {
    const float* za = (const float*)d_in[0];
    const float* zb = (const float*)d_in[1];
    float* out = (float*)d_out;

    stats_kernel<<<64, 128>>>(za, zb);
    gram_kernel<<<2 * NTILES * SPLITS, 256>>>(za, zb);
    cross_kernel<<<48, 256>>>();
    final_kernel<<<1, 128>>>(out);
}

// round 3
// speedup vs baseline: 2.3985x; 1.1488x over previous
#include <cuda_runtime.h>
#include <cuda_bf16.h>

#define N_ROWS 256
#define D_COLS 8192
#define LAMBDA 0.005f
#define SPLITS 24
#define NTILES 3            // symmetric 128x128 tile pairs: (0,0),(0,1),(1,1)
#define TILE_ELEMS 16384    // 128*128
#define LDB 40              // smem row stride in bf16 (80B=20 banks -> conflict-free ldmatrix)
#define NBLK 148            // one CTA per SM on sm_100a -> co-resident, safe grid barrier

// ---- scratch ----
__device__ __align__(16) float g_mu[2][D_COLS];
__device__ __align__(16) float g_inv[2][D_COLS];
__device__ float g_diag[128];
__device__ __align__(16) float g_GP[2][SPLITS][NTILES * TILE_ELEMS];  // 9.4 MB partials
__device__ float g_red[NBLK];
__device__ unsigned g_bar_count;   // zero-init
__device__ unsigned g_bar_gen;     // zero-init, monotonically increases across calls

// ---------------------------------------------------------------------------
// Software grid barrier. Safe: grid==NBLK==#SMs, 1 CTA/SM, all co-resident.
// ---------------------------------------------------------------------------
__device__ __forceinline__ void grid_sync() {
    __syncthreads();
    if (threadIdx.x == 0) {
        __threadfence();
        const unsigned gen = *(volatile unsigned*)&g_bar_gen;
        if (atomicAdd(&g_bar_count, 1u) == NBLK - 1) {
            g_bar_count = 0;
            __threadfence();
            *(volatile unsigned*)&g_bar_gen = gen + 1;
        } else {
            while (*(volatile unsigned*)&g_bar_gen == gen) {}
        }
        __threadfence();
    }
    __syncthreads();
}

__device__ __forceinline__ void mma_bf16(float* c, const unsigned* a, unsigned b0, unsigned b1) {
    asm volatile(
        "mma.sync.aligned.m16n8k16.row.col.f32.bf16.bf16.f32 "
        "{%0,%1,%2,%3}, {%4,%5,%6,%7}, {%8,%9}, {%0,%1,%2,%3};\n"
        : "+f"(c[0]), "+f"(c[1]), "+f"(c[2]), "+f"(c[3])
        : "r"(a[0]), "r"(a[1]), "r"(a[2]), "r"(a[3]), "r"(b0), "r"(b1));
}
__device__ __forceinline__ void ldm4(unsigned* r, unsigned addr) {
    asm volatile("ldmatrix.sync.aligned.m8n8.x4.shared.b16 {%0,%1,%2,%3}, [%4];\n"
        : "=r"(r[0]), "=r"(r[1]), "=r"(r[2]), "=r"(r[3]) : "r"(addr));
}

// ---------------------------------------------------------------------------
// One persistent kernel, 4 phases separated by grid_sync.
// ---------------------------------------------------------------------------
__global__ __launch_bounds__(256, 1)
void fused_kernel(const float* __restrict__ za, const float* __restrict__ zb,
                  float* __restrict__ out) {
    __shared__ __align__(16) __nv_bfloat16 sA[128 * LDB];
    __shared__ __align__(16) __nv_bfloat16 sB[128 * LDB];
    __shared__ __align__(16) float s_st[4][64 * 5];   // stats partials
    __shared__ float s_red[256];

    const int bid = blockIdx.x;
    const int tid = threadIdx.x;

    // ===================== Phase 0: column stats + diag term ================
    if (bid < 128) {
        const int c = tid & 63;
        const int gq = tid >> 6;          // row quarter 0..3
        const int col = bid * 64 + c;
        const float* __restrict__ pa = za + (gq * 64) * D_COLS + col;
        const float* __restrict__ pb = zb + (gq * 64) * D_COLS + col;
        float sa = 0.f, sb = 0.f, saa = 0.f, sbb = 0.f, sab = 0.f;
#pragma unroll 8
        for (int n = 0; n < 64; ++n) {
            float a = pa[n * D_COLS];
            float b = pb[n * D_COLS];
            sa += a; sb += b;
            saa += a * a; sbb += b * b; sab += a * b;
        }
        s_st[gq][c * 5 + 0] = sa;
        s_st[gq][c * 5 + 1] = sb;
        s_st[gq][c * 5 + 2] = saa;
        s_st[gq][c * 5 + 3] = sbb;
        s_st[gq][c * 5 + 4] = sab;
        __syncthreads();

        float term = 0.f;
        if (tid < 64) {
            float t0 = 0.f, t1 = 0.f, t2 = 0.f, t3 = 0.f, t4 = 0.f;
#pragma unroll
            for (int g = 0; g < 4; ++g) {
                t0 += s_st[g][tid * 5 + 0];
                t1 += s_st[g][tid * 5 + 1];
                t2 += s_st[g][tid * 5 + 2];
                t3 += s_st[g][tid * 5 + 3];
                t4 += s_st[g][tid * 5 + 4];
            }
            const int gcol = bid * 64 + tid;
            const float mua = t0 * (1.f / 256.f);
            const float mub = t1 * (1.f / 256.f);
            const float ia = rsqrtf((t2 - t0 * mua) * (1.f / 255.f));
            const float ib = rsqrtf((t3 - t1 * mub) * (1.f / 255.f));
            g_mu[0][gcol] = mua; g_inv[0][gcol] = ia;
            g_mu[1][gcol] = mub; g_inv[1][gcol] = ib;
            const float cdd = (t4 - 256.f * mua * mub) * ia * ib * (1.f / 256.f);
            term = (cdd - 1.f) * (cdd - 1.f) - LAMBDA * cdd * cdd;
        }
        s_red[tid] = term;
        __syncthreads();
#pragma unroll
        for (int off = 32; off > 0; off >>= 1) {   // only tids 0..63 have data
            if (tid < off) s_red[tid] += s_red[tid + off];
            __syncthreads();
        }
        if (tid == 0) g_diag[bid] = s_red[0];
    }

    grid_sync();

    // ===================== Phase 1: tensor-core Gram partials ===============
    if (bid < 2 * NTILES * SPLITS) {
        const int sel = bid / (NTILES * SPLITS);
        const int rem = bid % (NTILES * SPLITS);
        const int pair = rem / SPLITS;
        const int s = rem % SPLITS;

        const float* __restrict__ Z = sel ? zb : za;
        const float* __restrict__ mu = g_mu[sel];
        const float* __restrict__ iv = g_inv[sel];

        const int m0 = (pair == 2) ? 128 : 0;
        const int n0 = (pair == 0) ? 0 : 128;

        const int ks = (s < 16) ? s * 11 : 176 + (s - 16) * 10;
        const int kn = (s < 16) ? 11 : 10;

        const int warp = tid >> 5;
        const int lane = tid & 31;
        const int wm = warp & 3;
        const int wn = warp >> 2;

        float acc[2][8][4];
#pragma unroll
        for (int i = 0; i < 2; ++i)
#pragma unroll
            for (int j = 0; j < 8; ++j)
#pragma unroll
                for (int k = 0; k < 4; ++k) acc[i][j][k] = 0.f;

        const unsigned aBase = (unsigned)__cvta_generic_to_shared(sA);
        const unsigned bBase = (unsigned)__cvta_generic_to_shared(sB);
        const int laR = (lane & 7) + (lane & 8);
        const int laC = (lane >> 1) & 8;
        const int lbR = (lane & 7) + ((lane >> 1) & 8);
        const int lbC = (lane & 8);
        const unsigned aAddr = aBase + (unsigned)(((wm * 32 + laR) * LDB + laC) * 2);
        const unsigned bAddr = bBase + (unsigned)(((wn * 64 + lbR) * LDB + lbC) * 2);

        const float* __restrict__ Zm = Z + m0 * D_COLS;
        const float* __restrict__ Zn = Z + n0 * D_COLS;

        for (int it = 0; it < kn; ++it) {
            const int k0 = (ks + it) * 32;
#pragma unroll
            for (int l = 0; l < 4; ++l) {
                const int f = l * 256 + tid;
                const int row = f >> 3;
                const int c4 = f & 7;
                const int kg = k0 + c4 * 4;
                const float4 mm = *(const float4*)&mu[kg];
                const float4 ww = *(const float4*)&iv[kg];

                float4 va = *(const float4*)&Zm[row * D_COLS + kg];
                union { __nv_bfloat162 h2[2]; uint2 u; } pa;
                pa.h2[0] = __floats2bfloat162_rn((va.x - mm.x) * ww.x, (va.y - mm.y) * ww.y);
                pa.h2[1] = __floats2bfloat162_rn((va.z - mm.z) * ww.z, (va.w - mm.w) * ww.w);
                *(uint2*)&sA[row * LDB + c4 * 4] = pa.u;

                float4 vb = *(const float4*)&Zn[row * D_COLS + kg];
                union { __nv_bfloat162 h2[2]; uint2 u; } pb;
                pb.h2[0] = __floats2bfloat162_rn((vb.x - mm.x) * ww.x, (vb.y - mm.y) * ww.y);
                pb.h2[1] = __floats2bfloat162_rn((vb.z - mm.z) * ww.z, (vb.w - mm.w) * ww.w);
                *(uint2*)&sB[row * LDB + c4 * 4] = pb.u;
            }
            __syncthreads();
#pragma unroll
            for (int kf = 0; kf < 2; ++kf) {
                unsigned A0[4], A1[4];
                ldm4(A0, aAddr + (unsigned)((kf * 16) * 2));
                ldm4(A1, aAddr + (unsigned)((16 * LDB + kf * 16) * 2));
#pragma unroll
                for (int fp = 0; fp < 4; ++fp) {
                    unsigned B[4];
                    ldm4(B, bAddr + (unsigned)((fp * 16 * LDB + kf * 16) * 2));
                    mma_bf16(acc[0][2 * fp],     A0, B[0], B[1]);
                    mma_bf16(acc[0][2 * fp + 1], A0, B[2], B[3]);
                    mma_bf16(acc[1][2 * fp],     A1, B[0], B[1]);
                    mma_bf16(acc[1][2 * fp + 1], A1, B[2], B[3]);
                }
            }
            __syncthreads();
        }

        float* __restrict__ outp = &g_GP[sel][s][pair * TILE_ELEMS];
#pragma unroll
        for (int fm = 0; fm < 2; ++fm)
#pragma unroll
            for (int fn = 0; fn < 8; ++fn) {
                const int i = wm * 32 + fm * 16 + (lane >> 2);
                const int j = wn * 64 + fn * 8 + (lane & 3) * 2;
                float2 lo = {acc[fm][fn][0], acc[fm][fn][1]};
                float2 hi = {acc[fm][fn][2], acc[fm][fn][3]};
                *(float2*)&outp[i * 128 + j] = lo;
                *(float2*)&outp[(i + 8) * 128 + j] = hi;
            }
    }

    grid_sync();

    // ===================== Phase 2: cross reduction =========================
    {
        const int t = bid * 256 + tid;     // float4 task id
        float v = 0.f;
        if (t < 3 * TILE_ELEMS / 4) {      // 12288 tasks
            const int pair = t >> 12;
            const float w = (pair == 1) ? 2.f : 1.f;
            float4 ga = {0.f, 0.f, 0.f, 0.f}, gb = {0.f, 0.f, 0.f, 0.f};
#pragma unroll
            for (int s = 0; s < SPLITS; ++s) {
                const float4 a = *(const float4*)&g_GP[0][s][t * 4];
                const float4 bb = *(const float4*)&g_GP[1][s][t * 4];
                ga.x += a.x; ga.y += a.y; ga.z += a.z; ga.w += a.w;
                gb.x += bb.x; gb.y += bb.y; gb.z += bb.z; gb.w += bb.w;
            }
            v = w * (ga.x * gb.x + ga.y * gb.y + ga.z * gb.z + ga.w * gb.w);
        }
        __syncthreads();                    // s_red reuse safety
        s_red[tid] = v;
        __syncthreads();
#pragma unroll
        for (int off = 128; off > 0; off >>= 1) {
            if (tid < off) s_red[tid] += s_red[tid + off];
            __syncthreads();
        }
        if (tid == 0) g_red[bid] = s_red[0];
    }

    grid_sync();

    // ===================== Phase 3: final combine ===========================
    if (bid == 0) {
        float v = 0.f;
        if (tid < NBLK) v = g_red[tid] * (LAMBDA / (256.f * 256.f));
        if (tid < 128) v += g_diag[tid];
        __syncthreads();
        s_red[tid] = v;
        __syncthreads();
#pragma unroll
        for (int off = 128; off > 0; off >>= 1) {
            if (tid < off) s_red[tid] += s_red[tid + off];
            __syncthreads();
        }
        if (tid == 0) out[0] = s_red[0];
    }
}

// ---------------------------------------------------------------------------
extern "C" void kernel_launch(void* const* d_in, const int* in_sizes, int n_in,
                              void* d_out, int out_size) {
    const float* za = (const float*)d_in[0];
    const float* zb = (const float*)d_in[1];
    float* out = (float*)d_out;
    fused_kernel<<<NBLK, 256>>>(za, zb, out);
}

// round 4
// speedup vs baseline: 2.5640x; 1.0690x over previous
#include <cuda_runtime.h>
#include <cuda_bf16.h>

#define N_ROWS 256
#define D_COLS 8192
#define LAMBDA 0.005f
#define SPLITS 24
#define NTILES 3            // symmetric 128x128 tile pairs: (0,0),(0,1),(1,1)
#define TILE_ELEMS 16384
#define LDB 40              // smem row stride in bf16 (80B) -> conflict-free ldmatrix, 8B-aligned rows
#define NBLK 148

// ---- scratch ----
__device__ __align__(16) __nv_bfloat16 g_Zn[2][N_ROWS * D_COLS];      // normalized bf16, 8 MB
__device__ float g_diag[128];
__device__ __align__(16) float g_GP[2][SPLITS][NTILES * TILE_ELEMS];  // 9.4 MB partials
__device__ float g_red[NBLK];
__device__ unsigned g_bar_count;
__device__ unsigned g_bar_gen;

// ---------------------------------------------------------------------------
__device__ __forceinline__ void grid_sync() {
    __syncthreads();
    if (threadIdx.x == 0) {
        __threadfence();
        const unsigned gen = *(volatile unsigned*)&g_bar_gen;
        if (atomicAdd(&g_bar_count, 1u) == NBLK - 1) {
            g_bar_count = 0;
            __threadfence();
            *(volatile unsigned*)&g_bar_gen = gen + 1;
        } else {
            while (*(volatile unsigned*)&g_bar_gen == gen) {}
        }
        __threadfence();
    }
    __syncthreads();
}

__device__ __forceinline__ void mma_bf16(float* c, const unsigned* a, unsigned b0, unsigned b1) {
    asm volatile(
        "mma.sync.aligned.m16n8k16.row.col.f32.bf16.bf16.f32 "
        "{%0,%1,%2,%3}, {%4,%5,%6,%7}, {%8,%9}, {%0,%1,%2,%3};\n"
        : "+f"(c[0]), "+f"(c[1]), "+f"(c[2]), "+f"(c[3])
        : "r"(a[0]), "r"(a[1]), "r"(a[2]), "r"(a[3]), "r"(b0), "r"(b1));
}
__device__ __forceinline__ void ldm4(unsigned* r, unsigned addr) {
    asm volatile("ldmatrix.sync.aligned.m8n8.x4.shared.b16 {%0,%1,%2,%3}, [%4];\n"
        : "=r"(r[0]), "=r"(r[1]), "=r"(r[2]), "=r"(r[3]) : "r"(addr));
}
__device__ __forceinline__ void cp_async8(unsigned dst, const void* src) {
    asm volatile("cp.async.ca.shared.global [%0], [%1], 8;\n" :: "r"(dst), "l"(src));
}

// smem buffer layout (overlaid between phases):
//   gram:  A[2][128*LDB] bf16 (20480 B) then B[2][128*LDB] bf16 (20480 B) = 40960 B
//   stats: st[4][64*5] f32 (5120 B), mu[2][64] f32, inv[2][64] f32
#define SB_BYTES 40960
#define A_BUF_BYTES 10240   // 128*LDB*2

__global__ __launch_bounds__(256, 1)
void fused_kernel(const float* __restrict__ za, const float* __restrict__ zb,
                  float* __restrict__ out) {
    __shared__ __align__(16) unsigned char s_buf[SB_BYTES];
    __shared__ float s_red[256];

    const int bid = blockIdx.x;
    const int tid = threadIdx.x;

    // ===================== Phase 0: stats + normalize + diag ================
    if (bid < 128) {
        float (*s_st)[64 * 5] = (float (*)[64 * 5])s_buf;                 // [4][320]
        float* s_mu = (float*)(s_buf + 5120);                              // [2][64]
        float* s_inv = (float*)(s_buf + 5120 + 512);                       // [2][64]

        const int c = tid & 63;
        const int gq = tid >> 6;
        const int col = bid * 64 + c;
        const float* __restrict__ pa = za + (size_t)(gq * 64) * D_COLS + col;
        const float* __restrict__ pb = zb + (size_t)(gq * 64) * D_COLS + col;
        float sa = 0.f, sb = 0.f, saa = 0.f, sbb = 0.f, sab = 0.f;
#pragma unroll 8
        for (int n = 0; n < 64; ++n) {
            float a = pa[n * D_COLS];
            float b = pb[n * D_COLS];
            sa += a; sb += b;
            saa += a * a; sbb += b * b; sab += a * b;
        }
        s_st[gq][c * 5 + 0] = sa;
        s_st[gq][c * 5 + 1] = sb;
        s_st[gq][c * 5 + 2] = saa;
        s_st[gq][c * 5 + 3] = sbb;
        s_st[gq][c * 5 + 4] = sab;
        __syncthreads();

        float term = 0.f;
        if (tid < 64) {
            float t0 = 0.f, t1 = 0.f, t2 = 0.f, t3 = 0.f, t4 = 0.f;
#pragma unroll
            for (int g = 0; g < 4; ++g) {
                t0 += s_st[g][tid * 5 + 0];
                t1 += s_st[g][tid * 5 + 1];
                t2 += s_st[g][tid * 5 + 2];
                t3 += s_st[g][tid * 5 + 3];
                t4 += s_st[g][tid * 5 + 4];
            }
            const float mua = t0 * (1.f / 256.f);
            const float mub = t1 * (1.f / 256.f);
            const float ia = rsqrtf((t2 - t0 * mua) * (1.f / 255.f));
            const float ib = rsqrtf((t3 - t1 * mub) * (1.f / 255.f));
            const float cdd = (t4 - 256.f * mua * mub) * ia * ib * (1.f / 256.f);
            term = (cdd - 1.f) * (cdd - 1.f) - LAMBDA * cdd * cdd;
            s_mu[tid] = mua; s_mu[64 + tid] = mub;
            s_inv[tid] = ia; s_inv[64 + tid] = ib;
        }
        s_red[tid] = term;
        __syncthreads();
#pragma unroll
        for (int off = 32; off > 0; off >>= 1) {
            if (tid < off) s_red[tid] += s_red[tid + off];
            __syncthreads();
        }
        if (tid == 0) g_diag[bid] = s_red[0];

        // normalize: re-read slab (L2-hot), write bf16. thread = (rowgroup, colpair)
        const int cp2 = tid & 31;             // col pair 0..31
        const int rg = tid >> 5;              // row group 0..7 (32 rows each)
        const int lc = cp2 * 2;               // local col
        const int gcol = bid * 64 + lc;
        const float ma0 = s_mu[lc],      ma1 = s_mu[lc + 1];
        const float wa0 = s_inv[lc],     wa1 = s_inv[lc + 1];
        const float mb0 = s_mu[64 + lc], mb1 = s_mu[64 + lc + 1];
        const float wb0 = s_inv[64 + lc], wb1 = s_inv[64 + lc + 1];
        const float* __restrict__ qa = za + (size_t)(rg * 32) * D_COLS + gcol;
        const float* __restrict__ qb = zb + (size_t)(rg * 32) * D_COLS + gcol;
        __nv_bfloat16* __restrict__ oa = g_Zn[0] + (size_t)(rg * 32) * D_COLS + gcol;
        __nv_bfloat16* __restrict__ ob = g_Zn[1] + (size_t)(rg * 32) * D_COLS + gcol;
#pragma unroll 4
        for (int n = 0; n < 32; ++n) {
            float2 va = *(const float2*)&qa[n * D_COLS];
            float2 vb = *(const float2*)&qb[n * D_COLS];
            *(__nv_bfloat162*)&oa[n * D_COLS] =
                __floats2bfloat162_rn((va.x - ma0) * wa0, (va.y - ma1) * wa1);
            *(__nv_bfloat162*)&ob[n * D_COLS] =
                __floats2bfloat162_rn((vb.x - mb0) * wb0, (vb.y - mb1) * wb1);
        }
    }

    grid_sync();

    // ===================== Phase 1: cp.async tensor-core Gram ===============
    if (bid < 2 * NTILES * SPLITS) {
        const int sel = bid / (NTILES * SPLITS);
        const int rem = bid % (NTILES * SPLITS);
        const int pair = rem / SPLITS;
        const int s = rem % SPLITS;

        const int m0 = (pair == 2) ? 128 : 0;
        const int n0 = (pair == 0) ? 0 : 128;
        const int ks = (s < 16) ? s * 11 : 176 + (s - 16) * 10;  // 256 k-iters of 32
        const int kn = (s < 16) ? 11 : 10;

        const __nv_bfloat16* __restrict__ gA = g_Zn[sel] + (size_t)m0 * D_COLS;
        const __nv_bfloat16* __restrict__ gB = g_Zn[sel] + (size_t)n0 * D_COLS;

        const int warp = tid >> 5;
        const int lane = tid & 31;
        const int wm = warp & 3;
        const int wn = warp >> 2;

        float acc[2][8][4];
#pragma unroll
        for (int i = 0; i < 2; ++i)
#pragma unroll
            for (int j = 0; j < 8; ++j)
#pragma unroll
                for (int k = 0; k < 4; ++k) acc[i][j][k] = 0.f;

        const unsigned sBase = (unsigned)__cvta_generic_to_shared(s_buf);
        const int laR = (lane & 7) + (lane & 8);
        const int laC = (lane >> 1) & 8;
        const int lbR = (lane & 7) + ((lane >> 1) & 8);
        const int lbC = (lane & 8);
        const unsigned aAddr = sBase + (unsigned)(((wm * 32 + laR) * LDB + laC) * 2);
        const unsigned bAddr = sBase + 2u * A_BUF_BYTES + (unsigned)(((wn * 64 + lbR) * LDB + lbC) * 2);

        // stage: copy A/B 128x32 bf16 tiles via cp.async (8B chunks)
        // l = i*256+tid: side=l>>10, r=(l>>3)&127, c8=l&7
        const int st_r = (tid >> 3) & 127;   // constant per thread across i (tid<256 -> (i*256+tid)>>3 & 127 varies!)
        (void)st_r;

#define STAGE(bufv, k0v)                                                          \
        {                                                                         \
            const int k0_ = (k0v);                                                \
            const unsigned bo_ = (unsigned)(bufv) * A_BUF_BYTES;                  \
            _Pragma("unroll")                                                     \
            for (int i_ = 0; i_ < 8; ++i_) {                                      \
                const int l_ = i_ * 256 + tid;                                    \
                const int side_ = l_ >> 10;                                       \
                const int r_ = (l_ >> 3) & 127;                                   \
                const int c8_ = l_ & 7;                                           \
                const __nv_bfloat16* src_ = (side_ ? gB : gA) + (size_t)r_ * D_COLS + k0_ + c8_ * 4; \
                const unsigned dst_ = sBase + (unsigned)side_ * (2u * A_BUF_BYTES) + bo_             \
                                      + (unsigned)(r_ * (LDB * 2) + c8_ * 8);     \
                cp_async8(dst_, src_);                                            \
            }                                                                     \
            asm volatile("cp.async.commit_group;\n");                             \
        }

        STAGE(0, ks * 32);
        int buf = 0;
        for (int it = 0; it < kn; ++it) {
            if (it + 1 < kn) {
                STAGE(buf ^ 1, (ks + it + 1) * 32);
                asm volatile("cp.async.wait_group 1;\n");
            } else {
                asm volatile("cp.async.wait_group 0;\n");
            }
            __syncthreads();

            const unsigned off = (unsigned)buf * A_BUF_BYTES;
#pragma unroll
            for (int kf = 0; kf < 2; ++kf) {
                unsigned A0[4], A1[4];
                ldm4(A0, aAddr + off + (unsigned)(kf * 32));
                ldm4(A1, aAddr + off + (unsigned)(16 * LDB * 2 + kf * 32));
#pragma unroll
                for (int fp = 0; fp < 4; ++fp) {
                    unsigned B[4];
                    ldm4(B, bAddr + off + (unsigned)(fp * 16 * LDB * 2 + kf * 32));
                    mma_bf16(acc[0][2 * fp],     A0, B[0], B[1]);
                    mma_bf16(acc[0][2 * fp + 1], A0, B[2], B[3]);
                    mma_bf16(acc[1][2 * fp],     A1, B[0], B[1]);
                    mma_bf16(acc[1][2 * fp + 1], A1, B[2], B[3]);
                }
            }
            __syncthreads();
            buf ^= 1;
        }
#undef STAGE

        float* __restrict__ outp = &g_GP[sel][s][pair * TILE_ELEMS];
#pragma unroll
        for (int fm = 0; fm < 2; ++fm)
#pragma unroll
            for (int fn = 0; fn < 8; ++fn) {
                const int i = wm * 32 + fm * 16 + (lane >> 2);
                const int j = wn * 64 + fn * 8 + (lane & 3) * 2;
                float2 lo = {acc[fm][fn][0], acc[fm][fn][1]};
                float2 hi = {acc[fm][fn][2], acc[fm][fn][3]};
                *(float2*)&outp[i * 128 + j] = lo;
                *(float2*)&outp[(i + 8) * 128 + j] = hi;
            }
    }

    grid_sync();

    // ===================== Phase 2: cross reduction =========================
    {
        const int t = bid * 256 + tid;
        float v = 0.f;
        if (t < 3 * TILE_ELEMS / 4) {
            const int pair = t >> 12;
            const float w = (pair == 1) ? 2.f : 1.f;
            float4 ga = {0.f, 0.f, 0.f, 0.f}, gb = {0.f, 0.f, 0.f, 0.f};
#pragma unroll
            for (int s = 0; s < SPLITS; ++s) {
                const float4 a = *(const float4*)&g_GP[0][s][t * 4];
                const float4 bb = *(const float4*)&g_GP[1][s][t * 4];
                ga.x += a.x; ga.y += a.y; ga.z += a.z; ga.w += a.w;
                gb.x += bb.x; gb.y += bb.y; gb.z += bb.z; gb.w += bb.w;
            }
            v = w * (ga.x * gb.x + ga.y * gb.y + ga.z * gb.z + ga.w * gb.w);
        }
        __syncthreads();
        s_red[tid] = v;
        __syncthreads();
#pragma unroll
        for (int off = 128; off > 0; off >>= 1) {
            if (tid < off) s_red[tid] += s_red[tid + off];
            __syncthreads();
        }
        if (tid == 0) g_red[bid] = s_red[0];
    }

    grid_sync();

    // ===================== Phase 3: final combine ===========================
    if (bid == 0) {
        float v = 0.f;
        if (tid < NBLK) v = g_red[tid] * (LAMBDA / (256.f * 256.f));
        if (tid < 128) v += g_diag[tid];
        __syncthreads();
        s_red[tid] = v;
        __syncthreads();
#pragma unroll
        for (int off = 128; off > 0; off >>= 1) {
            if (tid < off) s_red[tid] += s_red[tid + off];
            __syncthreads();
        }
        if (tid == 0) out[0] = s_red[0];
    }
}

// ---------------------------------------------------------------------------
extern "C" void kernel_launch(void* const* d_in, const int* in_sizes, int n_in,
                              void* d_out, int out_size) {
    const float* za = (const float*)d_in[0];
    const float* zb = (const float*)d_in[1];
    float* out = (float*)d_out;
    fused_kernel<<<NBLK, 256>>>(za, zb, out);
}

// round 5
// speedup vs baseline: 2.6586x; 1.0369x over previous
#include <cuda_runtime.h>
#include <cuda_bf16.h>

#define N_ROWS 256
#define D_COLS 8192
#define LAMBDA 0.005f
#define SPLITS 24
#define NTILES 3            // symmetric 128x128 tile pairs: (0,0),(0,1),(1,1)
#define TILE_ELEMS 16384
#define LDB 40              // smem row stride in bf16 (80B) -> conflict-free ldmatrix, 8B-aligned rows
#define NBLK 148
#define NTHR 512

// ---- scratch ----
__device__ __align__(16) __nv_bfloat16 g_Zn[2][N_ROWS * D_COLS];      // normalized bf16, 8 MB
__device__ float g_diag[128];
__device__ __align__(16) float g_GP[2][SPLITS][NTILES * TILE_ELEMS];  // 9.4 MB partials
__device__ float g_red[NBLK];
__device__ unsigned g_bar_count;
__device__ unsigned g_bar_gen;

// ---------------------------------------------------------------------------
__device__ __forceinline__ void grid_sync() {
    __syncthreads();
    if (threadIdx.x == 0) {
        __threadfence();
        const unsigned gen = *(volatile unsigned*)&g_bar_gen;
        if (atomicAdd(&g_bar_count, 1u) == NBLK - 1) {
            g_bar_count = 0;
            __threadfence();
            *(volatile unsigned*)&g_bar_gen = gen + 1;
        } else {
            while (*(volatile unsigned*)&g_bar_gen == gen) {}
        }
        __threadfence();
    }
    __syncthreads();
}

__device__ __forceinline__ void mma_bf16(float* c, const unsigned* a, unsigned b0, unsigned b1) {
    asm volatile(
        "mma.sync.aligned.m16n8k16.row.col.f32.bf16.bf16.f32 "
        "{%0,%1,%2,%3}, {%4,%5,%6,%7}, {%8,%9}, {%0,%1,%2,%3};\n"
        : "+f"(c[0]), "+f"(c[1]), "+f"(c[2]), "+f"(c[3])
        : "r"(a[0]), "r"(a[1]), "r"(a[2]), "r"(a[3]), "r"(b0), "r"(b1));
}
__device__ __forceinline__ void ldm4(unsigned* r, unsigned addr) {
    asm volatile("ldmatrix.sync.aligned.m8n8.x4.shared.b16 {%0,%1,%2,%3}, [%4];\n"
        : "=r"(r[0]), "=r"(r[1]), "=r"(r[2]), "=r"(r[3]) : "r"(addr));
}
__device__ __forceinline__ void cp_async8(unsigned dst, const void* src) {
    asm volatile("cp.async.ca.shared.global [%0], [%1], 8;\n" :: "r"(dst), "l"(src));
}

#define SB_BYTES 40960
#define A_BUF_BYTES 10240   // 128*LDB*2

__global__ __launch_bounds__(NTHR, 1)
void fused_kernel(const float* __restrict__ za, const float* __restrict__ zb,
                  float* __restrict__ out) {
    __shared__ __align__(16) unsigned char s_buf[SB_BYTES];
    __shared__ float s_red[NTHR];

    const int bid = blockIdx.x;
    const int tid = threadIdx.x;

    // ===================== Phase 0: stats + normalize + diag ================
    if (bid < 128) {
        float (*s_st)[64 * 5] = (float (*)[64 * 5])s_buf;                  // [8][320] = 10240 B
        float* s_mu = (float*)(s_buf + 10240);                             // [2][64]
        float* s_inv = (float*)(s_buf + 10240 + 512);                      // [2][64]

        const int c = tid & 63;
        const int gq = tid >> 6;          // row group 0..7 (32 rows each)
        const int col = bid * 64 + c;
        const float* __restrict__ pa = za + (size_t)(gq * 32) * D_COLS + col;
        const float* __restrict__ pb = zb + (size_t)(gq * 32) * D_COLS + col;
        float sa = 0.f, sb = 0.f, saa = 0.f, sbb = 0.f, sab = 0.f;
#pragma unroll 8
        for (int n = 0; n < 32; ++n) {
            float a = pa[n * D_COLS];
            float b = pb[n * D_COLS];
            sa += a; sb += b;
            saa += a * a; sbb += b * b; sab += a * b;
        }
        s_st[gq][c * 5 + 0] = sa;
        s_st[gq][c * 5 + 1] = sb;
        s_st[gq][c * 5 + 2] = saa;
        s_st[gq][c * 5 + 3] = sbb;
        s_st[gq][c * 5 + 4] = sab;
        __syncthreads();

        float term = 0.f;
        if (tid < 64) {
            float t0 = 0.f, t1 = 0.f, t2 = 0.f, t3 = 0.f, t4 = 0.f;
#pragma unroll
            for (int g = 0; g < 8; ++g) {
                t0 += s_st[g][tid * 5 + 0];
                t1 += s_st[g][tid * 5 + 1];
                t2 += s_st[g][tid * 5 + 2];
                t3 += s_st[g][tid * 5 + 3];
                t4 += s_st[g][tid * 5 + 4];
            }
            const float mua = t0 * (1.f / 256.f);
            const float mub = t1 * (1.f / 256.f);
            const float ia = rsqrtf((t2 - t0 * mua) * (1.f / 255.f));
            const float ib = rsqrtf((t3 - t1 * mub) * (1.f / 255.f));
            const float cdd = (t4 - 256.f * mua * mub) * ia * ib * (1.f / 256.f);
            term = (cdd - 1.f) * (cdd - 1.f) - LAMBDA * cdd * cdd;
            s_mu[tid] = mua; s_mu[64 + tid] = mub;
            s_inv[tid] = ia; s_inv[64 + tid] = ib;
        }
        s_red[tid] = term;
        __syncthreads();
#pragma unroll
        for (int off = 32; off > 0; off >>= 1) {   // data only in tids 0..63
            if (tid < off) s_red[tid] += s_red[tid + off];
            __syncthreads();
        }
        if (tid == 0) g_diag[bid] = s_red[0];

        // normalize slab -> bf16 (L2-hot re-read). 16 row-groups x 32 col-pairs.
        const int cp2 = tid & 31;
        const int rg = tid >> 5;              // 0..15, 16 rows each
        const int lc = cp2 * 2;
        const int gcol = bid * 64 + lc;
        const float ma0 = s_mu[lc],       ma1 = s_mu[lc + 1];
        const float wa0 = s_inv[lc],      wa1 = s_inv[lc + 1];
        const float mb0 = s_mu[64 + lc],  mb1 = s_mu[64 + lc + 1];
        const float wb0 = s_inv[64 + lc], wb1 = s_inv[64 + lc + 1];
        const float* __restrict__ qa = za + (size_t)(rg * 16) * D_COLS + gcol;
        const float* __restrict__ qb = zb + (size_t)(rg * 16) * D_COLS + gcol;
        __nv_bfloat16* __restrict__ oa = g_Zn[0] + (size_t)(rg * 16) * D_COLS + gcol;
        __nv_bfloat16* __restrict__ ob = g_Zn[1] + (size_t)(rg * 16) * D_COLS + gcol;
#pragma unroll 4
        for (int n = 0; n < 16; ++n) {
            float2 va = *(const float2*)&qa[n * D_COLS];
            float2 vb = *(const float2*)&qb[n * D_COLS];
            *(__nv_bfloat162*)&oa[n * D_COLS] =
                __floats2bfloat162_rn((va.x - ma0) * wa0, (va.y - ma1) * wa1);
            *(__nv_bfloat162*)&ob[n * D_COLS] =
                __floats2bfloat162_rn((vb.x - mb0) * wb0, (vb.y - mb1) * wb1);
        }
    }

    grid_sync();

    // ===================== Phase 1: cp.async tensor-core Gram ===============
    // 16 warps: 4x4 warp grid, 32x32 warp tiles on a 128x128 block tile.
    if (bid < 2 * NTILES * SPLITS) {
        const int sel = bid / (NTILES * SPLITS);
        const int rem = bid % (NTILES * SPLITS);
        const int pair = rem / SPLITS;
        const int s = rem % SPLITS;

        const int m0 = (pair == 2) ? 128 : 0;
        const int n0 = (pair == 0) ? 0 : 128;
        const int ks = (s < 16) ? s * 11 : 176 + (s - 16) * 10;
        const int kn = (s < 16) ? 11 : 10;

        const __nv_bfloat16* __restrict__ gA = g_Zn[sel] + (size_t)m0 * D_COLS;
        const __nv_bfloat16* __restrict__ gB = g_Zn[sel] + (size_t)n0 * D_COLS;

        const int warp = tid >> 5;
        const int lane = tid & 31;
        const int wm = warp & 3;    // m strip of 32
        const int wn = warp >> 2;   // n strip of 32

        float acc[2][4][4];
#pragma unroll
        for (int i = 0; i < 2; ++i)
#pragma unroll
            for (int j = 0; j < 4; ++j)
#pragma unroll
                for (int k = 0; k < 4; ++k) acc[i][j][k] = 0.f;

        const unsigned sBase = (unsigned)__cvta_generic_to_shared(s_buf);
        const int laR = (lane & 7) + (lane & 8);
        const int laC = (lane >> 1) & 8;
        const int lbR = (lane & 7) + ((lane >> 1) & 8);
        const int lbC = (lane & 8);
        const unsigned aAddr = sBase + (unsigned)(((wm * 32 + laR) * LDB + laC) * 2);
        const unsigned bAddr = sBase + 2u * A_BUF_BYTES + (unsigned)(((wn * 32 + lbR) * LDB + lbC) * 2);

        // staging: 2048 8B chunks, 4 per thread
#define STAGE(bufv, k0v)                                                          \
        {                                                                         \
            const int k0_ = (k0v);                                                \
            const unsigned bo_ = (unsigned)(bufv) * A_BUF_BYTES;                  \
            _Pragma("unroll")                                                     \
            for (int i_ = 0; i_ < 4; ++i_) {                                      \
                const int l_ = i_ * NTHR + tid;                                   \
                const int side_ = l_ >> 10;                                       \
                const int r_ = (l_ >> 3) & 127;                                   \
                const int c8_ = l_ & 7;                                           \
                const __nv_bfloat16* src_ = (side_ ? gB : gA) + (size_t)r_ * D_COLS + k0_ + c8_ * 4; \
                const unsigned dst_ = sBase + (unsigned)side_ * (2u * A_BUF_BYTES) + bo_             \
                                      + (unsigned)(r_ * (LDB * 2) + c8_ * 8);     \
                cp_async8(dst_, src_);                                            \
            }                                                                     \
            asm volatile("cp.async.commit_group;\n");                             \
        }

        STAGE(0, ks * 32);
        int buf = 0;
        for (int it = 0; it < kn; ++it) {
            if (it + 1 < kn) {
                STAGE(buf ^ 1, (ks + it + 1) * 32);
                asm volatile("cp.async.wait_group 1;\n");
            } else {
                asm volatile("cp.async.wait_group 0;\n");
            }
            __syncthreads();

            const unsigned off = (unsigned)buf * A_BUF_BYTES;
#pragma unroll
            for (int kf = 0; kf < 2; ++kf) {
                unsigned A0[4], A1[4];
                ldm4(A0, aAddr + off + (unsigned)(kf * 32));
                ldm4(A1, aAddr + off + (unsigned)(16 * LDB * 2 + kf * 32));
#pragma unroll
                for (int fp = 0; fp < 2; ++fp) {
                    unsigned B[4];
                    ldm4(B, bAddr + off + (unsigned)(fp * 16 * LDB * 2 + kf * 32));
                    mma_bf16(acc[0][2 * fp],     A0, B[0], B[1]);
                    mma_bf16(acc[0][2 * fp + 1], A0, B[2], B[3]);
                    mma_bf16(acc[1][2 * fp],     A1, B[0], B[1]);
                    mma_bf16(acc[1][2 * fp + 1], A1, B[2], B[3]);
                }
            }
            __syncthreads();
            buf ^= 1;
        }
#undef STAGE

        float* __restrict__ outp = &g_GP[sel][s][pair * TILE_ELEMS];
#pragma unroll
        for (int fm = 0; fm < 2; ++fm)
#pragma unroll
            for (int fn = 0; fn < 4; ++fn) {
                const int i = wm * 32 + fm * 16 + (lane >> 2);
                const int j = wn * 32 + fn * 8 + (lane & 3) * 2;
                float2 lo = {acc[fm][fn][0], acc[fm][fn][1]};
                float2 hi = {acc[fm][fn][2], acc[fm][fn][3]};
                *(float2*)&outp[i * 128 + j] = lo;
                *(float2*)&outp[(i + 8) * 128 + j] = hi;
            }
    }

    grid_sync();

    // ===================== Phase 2: cross reduction =========================
    {
        const int t = bid * NTHR + tid;    // float4 task id
        float v = 0.f;
        if (t < 3 * TILE_ELEMS / 4) {      // 12288 tasks -> blocks 0..23
            const int pair = t >> 12;
            const float w = (pair == 1) ? 2.f : 1.f;
            float4 ga = {0.f, 0.f, 0.f, 0.f}, gb = {0.f, 0.f, 0.f, 0.f};
#pragma unroll
            for (int s = 0; s < SPLITS; ++s) {
                const float4 a = *(const float4*)&g_GP[0][s][t * 4];
                const float4 bb = *(const float4*)&g_GP[1][s][t * 4];
                ga.x += a.x; ga.y += a.y; ga.z += a.z; ga.w += a.w;
                gb.x += bb.x; gb.y += bb.y; gb.z += bb.z; gb.w += bb.w;
            }
            v = w * (ga.x * gb.x + ga.y * gb.y + ga.z * gb.z + ga.w * gb.w);
        }
        __syncthreads();
        s_red[tid] = v;
        __syncthreads();
#pragma unroll
        for (int off = 256; off > 0; off >>= 1) {
            if (tid < off) s_red[tid] += s_red[tid + off];
            __syncthreads();
        }
        if (tid == 0) g_red[bid] = s_red[0];
    }

    grid_sync();

    // ===================== Phase 3: final combine ===========================
    if (bid == 0) {
        float v = 0.f;
        if (tid < NBLK) v = g_red[tid] * (LAMBDA / (256.f * 256.f));
        if (tid < 128) v += g_diag[tid];
        __syncthreads();
        s_red[tid] = v;
        __syncthreads();
#pragma unroll
        for (int off = 256; off > 0; off >>= 1) {
            if (tid < off) s_red[tid] += s_red[tid + off];
            __syncthreads();
        }
        if (tid == 0) out[0] = s_red[0];
    }
}

// ---------------------------------------------------------------------------
extern "C" void kernel_launch(void* const* d_in, const int* in_sizes, int n_in,
                              void* d_out, int out_size) {
    const float* za = (const float*)d_in[0];
    const float* zb = (const float*)d_in[1];
    float* out = (float*)d_out;
    fused_kernel<<<NBLK, NTHR>>>(za, zb, out);
}